// round 9
// baseline (speedup 1.0000x reference)
#include <cuda_runtime.h>

#define NEGV   -1.0e8f
#define BH     64                // band height (rows per CTA)
#define NB     16                // number of bands
#define GW     1025              // boundary row: columns 0..1024
#define NGROUPS 136              // groups of 8 steps; last active step s=1086

// G[b][j] = V[64b][j] over 4 states. Row 16 = final row i=1024.
__device__ float4 G[(NB + 1) * GW];
// PROG[b] = highest column j such that G[b][1..j] is published.
__device__ int PROG[NB + 1];

// ---------------------------------------------------------------------------
__global__ void init_kernel() {
    int i = threadIdx.x;
    if (i <= NB) PROG[i] = 0;
}

// ---------------------------------------------------------------------------
__device__ __forceinline__ int ldacq(const int* p) {
    int v;
    asm volatile("ld.acquire.gpu.s32 %0, [%1];" : "=r"(v) : "l"(p) : "memory");
    return v;
}
__device__ __forceinline__ void strel(int* p, int v) {
    asm volatile("st.release.gpu.s32 [%0], %1;" :: "l"(p), "r"(v) : "memory");
}
// Plain coherent 16B global load (NOT .nc: G is written by peer CTAs).
__device__ __forceinline__ float4 ldg4(const float4* p) {
    float4 v;
    asm volatile("ld.global.v4.f32 {%0,%1,%2,%3}, [%4];"
                 : "=f"(v.x), "=f"(v.y), "=f"(v.z), "=f"(v.w) : "l"(p) : "memory");
    return v;
}
#define BAR_DP()  asm volatile("bar.sync 1, 256;" ::: "memory")
#define BAR_ALL() asm volatile("bar.sync 2, 288;" ::: "memory")

// ---------------------------------------------------------------------------
// Persistent band DP. Grid = 16 blocks x 288 threads.
// Threads 0..255: DP. Thread = 4*a + t : cell a (row in band), state t.
// Threads 256..287: halo warp — prefetches the top-boundary row one group
// ahead into the smem ring Hring[p & 31] (p = boundary column position).
// Cell a computes column j = s - a + 1 at step s (active s in [a, a+1023]).
// Sources: up (t=1) Dm1[a]; left (t=2) Dm1[a+1]; diag (t=0,3) Dm2[a];
// for a==0, up = Hring[(s+1)&31], diag = Hring[s&31].
// ---------------------------------------------------------------------------
__global__ __launch_bounds__(288) void dp_kernel(const float* __restrict__ theta,
                                                 const float4* __restrict__ A4) {
    __shared__ float4 D[3][BH + 2];
    __shared__ float4 Hring[32];

    const int b   = blockIdx.x;
    const int tid = threadIdx.x;
    const float4 NEG4 = make_float4(NEGV, NEGV, NEGV, NEGV);
    const float4* Grow = G + b * GW;                   // top boundary (read)
    float*        Gout = (float*)(G + (b + 1) * GW);   // bottom row (write)

    if (tid < 3 * (BH + 2)) ((float4*)D)[tid] = NEG4;  // pre-active state

    if (tid >= 256) {
        // ===================== HALO WARP =====================
        const int lane = tid - 256;
        // Preloop: fill halo positions 0..9 (slots 0..9).
        if (b == 0) {
            if (lane < 10)
                Hring[lane] = (lane == 0) ? make_float4(0.f, 0.f, 0.f, 0.f)  // SEED
                                          : NEG4;
        } else {
            if (lane == 0) { int av = 0; while (av < 9) av = ldacq(PROG + b); }
            __syncwarp();
            if (lane < 10)
                Hring[lane] = (lane == 0) ? NEG4 : ldg4(Grow + lane);
        }
        BAR_ALL();                                     // publish initial ring

        for (int g = 0; g < NGROUPS; ++g) {
            if (g < NGROUPS - 1) {
                int base = 8 * (g + 1) + 2;            // halos for group g+1
                if (b != 0) {
                    int need = base + 7; need = need > 1024 ? 1024 : need;
                    if (lane == 0) { int av = 0; while (av < need) av = ldacq(PROG + b); }
                    __syncwarp();
                    if (lane < 8) {
                        int p = base + lane;
                        int pc = p > 1024 ? 1024 : p;
                        Hring[p & 31] = ldg4(Grow + pc);
                    }
                } else {
                    if (lane < 8) Hring[(base + lane) & 31] = NEG4;
                }
            }
            BAR_ALL();                                 // hand ring to DP warps
        }
        return;
    }

    // ===================== DP THREADS (0..255) =====================
    const int a = tid >> 2;
    const int t = tid & 3;
    const int r = BH * b + a;                          // theta/A row = i-1
    const bool relLane = (tid == 4 * (BH - 1));        // a=63, t=0
    const bool botWarp = ((tid >> 5) == 7);            // cells 56..63
    const bool bot     = (a == BH - 1);
    const bool topCell = (a == 0) && (t != 2);

    // A/theta register ring, depth 8: slot k holds data for step s, s&7==k.
    float4 Ar[8]; float Tr[8];
    #pragma unroll
    for (int k = 0; k < 8; ++k) {
        int col = k - a; col = col < 0 ? 0 : col;
        int idx = (r * 1024 + col) * 4 + t;
        Ar[k] = __ldg(A4 + idx);
        Tr[k] = __ldg(theta + idx);
    }

    BAR_ALL();                                         // initial ring ready

    float4* Pn  = D[0];
    float4* Pm1 = D[2];
    float4* Pm2 = D[1];

    for (int g = 0; g < NGROUPS; ++g) {
        #pragma unroll
        for (int k = 0; k < 8; ++k) {
            const int s = 8 * g + k;
            float4 av = Ar[k];
            float  tv = Tr[k];

            float4 s4;
            if (topCell) {
                s4 = (t == 1) ? Hring[(s + 1) & 31]    // up   = halo(s+1)
                              : Hring[s & 31];         // diag = halo(s)
            } else {
                const float4* sp = (t == 1) ? (Pm1 + a)
                                 : (t == 2) ? (Pm1 + a + 1)
                                            : (Pm2 + a);
                s4 = *sp;
            }

            float w0 = s4.x + av.x;
            float w1 = s4.y + av.y;
            float w2 = s4.z + av.z;
            float w3 = s4.w + av.w;
            float m = fmaxf(fmaxf(w0, w1), fmaxf(w2, w3));
            float sum = __expf(w0 - m) + __expf(w1 - m) +
                        __expf(w2 - m) + __expf(w3 - m);
            float res = m + __logf(sum) + tv;

            bool active = (s >= a) && (s <= a + 1023);
            if (active) {
                ((float*)(Pn + a + 1))[t] = res;
                if (bot) Gout[(s - (BH - 2)) * 4 + t] = res;   // col j = s-62
            }

            // refill ring for step s+8
            {
                int col = s + 8 - a;
                col = col < 0 ? 0 : (col > 1023 ? 1023 : col);
                int idx = (r * 1024 + col) * 4 + t;
                Ar[k] = __ldg(A4 + idx);
                Tr[k] = __ldg(theta + idx);
            }

            // bottom warp: order its lanes' Gout stores, publish watermark
            if (botWarp) {
                __syncwarp();
                if (relLane && (s >= BH - 1) && (s <= 1086))
                    strel(PROG + b + 1, s - (BH - 2));
            }

            if (k < 7) BAR_DP(); else BAR_ALL();       // group end syncs all

            float4* tmp = Pm2; Pm2 = Pm1; Pm1 = Pn; Pn = tmp;
        }
    }
}

// ---------------------------------------------------------------------------
// Stream-ordered after dp_kernel: plain read is safe.
__global__ void final_kernel(float* out) {
    float4 v = ldg4(G + NB * GW + 1024);               // V[1024][1024]
    float m = fmaxf(fmaxf(v.x, v.y), fmaxf(v.z, v.w));
    out[0] = m + __logf(__expf(v.x - m) + __expf(v.y - m) +
                        __expf(v.z - m) + __expf(v.w - m));
}

// ---------------------------------------------------------------------------
extern "C" void kernel_launch(void* const* d_in, const int* in_sizes, int n_in,
                              void* d_out, int out_size) {
    const float*  theta = (const float*)d_in[0];   // [1024,1024,4]
    const float4* A4    = (const float4*)d_in[1];  // [1024,1024,4,4]

    init_kernel<<<1, 64>>>();
    dp_kernel<<<NB, 288>>>(theta, A4);
    final_kernel<<<1, 1>>>((float*)d_out);
}